// round 16
// baseline (speedup 1.0000x reference)
#include <cuda_runtime.h>

// ---------------- problem dims ----------------
#define NPTS   4096
#define HDIM   64
#define ODIM   16
#define JSPLIT 16
#define JRANGE (NPTS / JSPLIT)   // 256 — whole range staged once

typedef unsigned long long ull;

// ---------------- dynamic smem layout (bytes) ----------------
#define OFF_SP   0                      // float4[256]  (4 KB)
#define OFF_SN   4096                   // float4[256]  (4 KB)
#define OFF_SFQ  8192                   // ull[256*32]  (64 KB)
#define OFF_A2   73728                  // float[512]
#define OFF_B2   75776                  // float[64]
#define OFF_A1   76032                  // float[24]
#define OFF_B1   76128                  // float[8]
#define OFF_QA   76160                  // ull[32]  per-h-pair scale
#define OFF_QB   76416                  // ull[32]  per-h-pair bias
#define OFF_ST   76672                  // float2[4]
#define SMEM_DYN 76736

// ---------------- f32x2 helpers ----------------
static __device__ __forceinline__ ull pk(float a, float b) {
    ull r; asm("mov.b64 %0, {%1, %2};" : "=l"(r) : "f"(a), "f"(b)); return r;
}
static __device__ __forceinline__ void upk(ull x, float& a, float& b) {
    asm("mov.b64 {%0, %1}, %2;" : "=f"(a), "=f"(b) : "l"(x));
}
static __device__ __forceinline__ ull fma2(ull a, ull b, ull c) {
    ull d; asm("fma.rn.f32x2 %0, %1, %2, %3;" : "=l"(d) : "l"(a), "l"(b), "l"(c)); return d;
}
static __device__ __forceinline__ ull mul2(ull a, ull b) {
    ull d; asm("mul.rn.f32x2 %0, %1, %2;" : "=l"(d) : "l"(a), "l"(b)); return d;
}
static __device__ __forceinline__ float ex2(float x) {
    float r; asm("ex2.approx.f32 %0, %1;" : "=f"(r) : "f"(x)); return r;
}
static __device__ __forceinline__ float leaky(float x) { return fmaxf(x, 0.2f * x); }

static __device__ __forceinline__ float warp_sum(float v) {
    #pragma unroll
    for (int o = 16; o; o >>= 1) v += __shfl_down_sync(0xffffffffu, v, o);
    return v;
}

// coords pre-scaled by S*sqrt(log2 e), M by 1/sqrt(log2 e): folds L2E into sq
#define SLC  0.84932180028801904f
#define MINV 0.83255461115769769f

// ---------------- scratch ----------------
__device__ float  g_fpre[NPTS * HDIM];
__device__ float4 g_respart4[JSPLIT * NPTS * HDIM / 4];
__device__ float  g_opre[NPTS * ODIM];
__device__ float  g_pin[32 * 8];
__device__ float  g_pout[32 * 8];

// ---------------- kernel 1: input MLP (16->64->64) + partial group stats ----------------
__global__ void k_infeat(const float* __restrict__ feat,
                         const float* __restrict__ W1, const float* __restrict__ b1,
                         const float* __restrict__ W2, const float* __restrict__ b2) {
    __shared__ float4 W1s[256];
    __shared__ float4 W2s[1024];
    __shared__ float  b1s[64], b2s[64];
    __shared__ float  red[4][8];
    int tid = threadIdx.x;
    for (int t = tid; t < 256;  t += 128) W1s[t] = ((const float4*)W1)[t];
    for (int t = tid; t < 1024; t += 128) W2s[t] = ((const float4*)W2)[t];
    if (tid < 64) { b1s[tid] = b1[tid]; b2s[tid] = b2[tid]; }
    __syncthreads();

    int p = blockIdx.x * 128 + tid;
    float f[16];
    #pragma unroll
    for (int k = 0; k < 16; k++) f[k] = feat[p * 16 + k];

    float t1[64];
    #pragma unroll
    for (int h = 0; h < 64; h++) {
        float s = b1s[h];
        #pragma unroll
        for (int k4 = 0; k4 < 4; k4++) {
            float4 w = W1s[h * 4 + k4];
            s = fmaf(w.x, f[k4*4+0], fmaf(w.y, f[k4*4+1], fmaf(w.z, f[k4*4+2], fmaf(w.w, f[k4*4+3], s))));
        }
        t1[h] = leaky(s);
    }

    float gs[4] = {0,0,0,0}, gq[4] = {0,0,0,0};
    for (int h = 0; h < 64; h++) {
        float s = b2s[h];
        #pragma unroll
        for (int k4 = 0; k4 < 16; k4++) {
            float4 w = W2s[h * 16 + k4];
            s = fmaf(w.x, t1[k4*4+0], fmaf(w.y, t1[k4*4+1], fmaf(w.z, t1[k4*4+2], fmaf(w.w, t1[k4*4+3], s))));
        }
        float v = leaky(s);
        g_fpre[p * 64 + h] = v;
        int g = h >> 4; gs[g] += v; gq[g] += v * v;
    }

    int w = tid >> 5, l = tid & 31;
    #pragma unroll
    for (int g = 0; g < 4; g++) {
        float s = warp_sum(gs[g]);
        float q = warp_sum(gq[g]);
        if (l == 0) { red[w][g*2] = s; red[w][g*2+1] = q; }
    }
    __syncthreads();
    if (tid < 8) g_pin[blockIdx.x * 8 + tid] = red[0][tid] + red[1][tid] + red[2][tid] + red[3][tid];
}

// ---------------- kernel 2: pairwise convolution (single-tile, 256-thread blocks) ----------------
// Warp = 8 i x 4 h-lanes; 8 warps/block share ONE tile staging (halves per-SM staging
// cost vs 2x128-thread blocks; same 8 warps/SM). Inner loop identical to R13.
__global__ void __launch_bounds__(256, 1) k_conv(
        const float* __restrict__ points, const float* __restrict__ nuvp,
        const float* __restrict__ A1, const float* __restrict__ B1,
        const float* __restrict__ A2, const float* __restrict__ B2,
        const float* __restrict__ gin, const float* __restrict__ bin) {
    extern __shared__ char smem[];
    float4* sp   = (float4*)(smem + OFF_SP);
    float4* sn   = (float4*)(smem + OFF_SN);
    ull*    sfq  = (ull*)   (smem + OFF_SFQ);
    float*  s_A2 = (float*) (smem + OFF_A2);
    float*  s_B2 = (float*) (smem + OFF_B2);
    float*  s_A1 = (float*) (smem + OFF_A1);
    float*  s_B1 = (float*) (smem + OFF_B1);
    ull*    s_a2 = (ull*)   (smem + OFF_QA);
    ull*    s_b2 = (ull*)   (smem + OFF_QB);
    float2* s_st = (float2*)(smem + OFF_ST);

    int tid = threadIdx.x;
    int warp = tid >> 5, lane = tid & 31, isub = lane & 7, hl = lane >> 3;
    int i  = blockIdx.x * 64 + warp * 8 + isub;
    int h0 = hl * 16;

    // ---- cooperative param staging (once per 8 warps) ----
    if (tid < 128) ((float4*)s_A2)[tid] = ((const float4*)A2)[tid];   // 512 floats
    if (tid < 16) ((float4*)s_B2)[tid] = ((const float4*)B2)[tid];
    if (tid < 24) s_A1[tid] = A1[tid];
    if (tid < 8)  s_B1[tid] = B1[tid];

    // ---- inline GroupNorm stats for f (deterministic fixed-order) ----
    if (tid < 4) {
        float s = 0.f, q = 0.f;
        for (int b = 0; b < 32; b++) { s += g_pin[b*8 + tid*2]; q += g_pin[b*8 + tid*2 + 1]; }
        float mu  = s * (1.0f / 65536.0f);
        float var = q * (1.0f / 65536.0f) - mu * mu;
        s_st[tid] = make_float2(mu, rsqrtf(var + 1e-5f));
    }
    __syncthreads();
    if (tid < 32) {
        int ha = tid * 2, hb = ha + 1;
        float2 sa = s_st[ha >> 4], sb = s_st[hb >> 4];
        float Aa = sa.y * gin[ha], Ab = sb.y * gin[hb];
        s_a2[tid] = pk(Aa, Ab);
        s_b2[tid] = pk(bin[ha] - sa.x * Aa, bin[hb] - sb.x * Ab);
    }

    float pix = points[3*i+0]*SLC, piy = points[3*i+1]*SLC, piz = points[3*i+2]*SLC;
    float nix = nuvp[9*i+0],       niy = nuvp[9*i+1],       niz = nuvp[9*i+2];
    float m2x = -2.0f*pix, m2y = -2.0f*piy, m2z = -2.0f*piz;
    float bsq = pix*pix + piy*piy + piz*piz;

    // M = (A1 @ nuv_i)/sqrt(log2 e); bb = B1 - M . ci   (params from smem)
    float M[8][3], bb[8];
    #pragma unroll
    for (int c = 0; c < 8; c++) {
        float a0 = s_A1[c*3+0], a1 = s_A1[c*3+1], a2c = s_A1[c*3+2];
        #pragma unroll
        for (int d = 0; d < 3; d++)
            M[c][d] = fmaf(a0, nuvp[9*i + d], fmaf(a1, nuvp[9*i + 3 + d], a2c * nuvp[9*i + 6 + d])) * MINV;
        bb[c] = s_B1[c] - (M[c][0]*pix + M[c][1]*piy + M[c][2]*piz);
    }

    // per-lane A2 slice (h-pairs) + B2, built from smem
    ull a2r[8][8];
    #pragma unroll
    for (int hp = 0; hp < 8; hp++)
        #pragma unroll
        for (int c = 0; c < 8; c++)
            a2r[c][hp] = pk(s_A2[(h0 + 2*hp) * 8 + c], s_A2[(h0 + 2*hp + 1) * 8 + c]);
    ull b2p[8];
    #pragma unroll
    for (int hp = 0; hp < 8; hp++) b2p[hp] = pk(s_B2[h0 + 2*hp], s_B2[h0 + 2*hp + 1]);

    ull acc[8];
    #pragma unroll
    for (int hp = 0; hp < 8; hp++) acc[hp] = pk(0.f, 0.f);

    // ---- stage whole j-range ONCE (256 threads, one pass) ----
    int j0 = blockIdx.y * JRANGE;
    if (tid < JRANGE) {
        int j = j0 + tid;
        float px = points[3*j]*SLC, py = points[3*j+1]*SLC, pz = points[3*j+2]*SLC;
        sp[tid] = make_float4(px, py, pz, px*px + py*py + pz*pz);
        sn[tid] = make_float4(nuvp[9*j], nuvp[9*j+1], nuvp[9*j+2], 0.f);
    }
    __syncthreads();   // s_a2/s_b2 visible for f staging
    for (int t = tid; t < JRANGE * 16; t += 256) {
        ulonglong2 r = ((const ulonglong2*)g_fpre)[(size_t)j0 * 16 + t];
        int hp2 = (t & 15) * 2;
        float a, b, c, d;
        upk(r.x, a, b); upk(r.y, c, d);
        float Aa, Ab, Ba, Bb, Ac, Ad, Bc, Bd;
        upk(s_a2[hp2], Aa, Ab);     upk(s_b2[hp2], Ba, Bb);
        upk(s_a2[hp2 + 1], Ac, Ad); upk(s_b2[hp2 + 1], Bc, Bd);
        ulonglong2 w2;
        w2.x = pk(fmaf(a, Aa, Ba), fmaf(b, Ab, Bb));
        w2.y = pk(fmaf(c, Ac, Bc), fmaf(d, Ad, Bd));
        ((ulonglong2*)sfq)[t] = w2;
    }
    __syncthreads();

    // ---- barrier-free mainloop over 256 j ----
    // prologue: scalar block for group 0, then prime the q=0 shuffles
    float wA, ysA[8];
    {
        float4 pj = sp[hl], nj = sn[hl];
        float sq = fmaf(m2x, pj.x, fmaf(m2y, pj.y, fmaf(m2z, pj.z, bsq + pj.w)));
        float dt = fmaf(nix, nj.x, fmaf(niy, nj.y, niz * nj.z));
        wA = ex2(sq * (2.0f - dt) * (dt - 2.0f));
        #pragma unroll
        for (int c = 0; c < 8; c++) {
            float y = fmaf(M[c][0], pj.x, fmaf(M[c][1], pj.y, fmaf(M[c][2], pj.z, bb[c])));
            ysA[c] = fmaxf(y, 0.f);
        }
    }
    float wvC = __shfl_sync(0xffffffffu, wA, isub);
    float yvC[8];
    #pragma unroll
    for (int c = 0; c < 8; c++) yvC[c] = __shfl_sync(0xffffffffu, ysA[c], isub);

    #pragma unroll 1
    for (int g = 0; g < JRANGE / 4; g++) {
        // ---- compute NEXT group's scalar block first (hides its latency) ----
        float wB, ysB[8];
        {
            int jn = (g + 1 < JRANGE / 4) ? (g + 1) * 4 + hl : hl;   // last iter: dummy
            float4 pj = sp[jn], nj = sn[jn];
            float sq = fmaf(m2x, pj.x, fmaf(m2y, pj.y, fmaf(m2z, pj.z, bsq + pj.w)));
            float dt = fmaf(nix, nj.x, fmaf(niy, nj.y, niz * nj.z));
            wB = ex2(sq * (2.0f - dt) * (dt - 2.0f));
            #pragma unroll
            for (int c = 0; c < 8; c++) {
                float y = fmaf(M[c][0], pj.x, fmaf(M[c][1], pj.y, fmaf(M[c][2], pj.z, bb[c])));
                ysB[c] = fmaxf(y, 0.f);
            }
        }

        // ---- consume 4 j's; shuffles for j+1 issued before j's matvec ----
        int jj4 = g * 4;
        #pragma unroll
        for (int q = 0; q < 4; q++) {
            // prefetch next j's scalars (q<3: group A src q+1; q==3: group B src 0)
            float wvN;
            float yvN[8];
            if (q < 3) {
                int src = isub + ((q + 1) << 3);
                wvN = __shfl_sync(0xffffffffu, wA, src);
                #pragma unroll
                for (int c = 0; c < 8; c++) yvN[c] = __shfl_sync(0xffffffffu, ysA[c], src);
            } else {
                wvN = __shfl_sync(0xffffffffu, wB, isub);
                #pragma unroll
                for (int c = 0; c < 8; c++) yvN[c] = __shfl_sync(0xffffffffu, ysB[c], isub);
            }

            int jj = jj4 + q;
            ull ys[8];
            #pragma unroll
            for (int c = 0; c < 8; c++) ys[c] = pk(yvC[c], yvC[c]);

            // matvec: G = A2.Y + B2, 8 independent packed chains
            ull gg[8];
            #pragma unroll
            for (int hp = 0; hp < 8; hp++) gg[hp] = fma2(a2r[0][hp], ys[0], b2p[hp]);
            #pragma unroll
            for (int c = 1; c < 8; c++)
                #pragma unroll
                for (int hp = 0; hp < 8; hp++) gg[hp] = fma2(a2r[c][hp], ys[c], gg[hp]);

            // epilogue: acc += relu(G) * f * w   (f via LDS.128)
            const ulonglong2* f2 = (const ulonglong2*)(sfq + jj * 32 + hl * 8);
            ulonglong2 fq0 = f2[0], fq1 = f2[1], fq2 = f2[2], fq3 = f2[3];
            ull frow[8] = {fq0.x, fq0.y, fq1.x, fq1.y, fq2.x, fq2.y, fq3.x, fq3.y};
            ull ws = pk(wvC, wvC);
            #pragma unroll
            for (int hp = 0; hp < 8; hp++) {
                float a, b; upk(gg[hp], a, b);
                a = fmaxf(a, 0.f); b = fmaxf(b, 0.f);
                acc[hp] = fma2(mul2(pk(a, b), frow[hp]), ws, acc[hp]);
            }

            wvC = wvN;
            #pragma unroll
            for (int c = 0; c < 8; c++) yvC[c] = yvN[c];
        }

        wA = wB;
        #pragma unroll
        for (int c = 0; c < 8; c++) ysA[c] = ysB[c];
    }

    float* rp = ((float*)g_respart4) + ((size_t)blockIdx.y * NPTS + i) * 64 + h0;
    #pragma unroll
    for (int hp = 0; hp < 8; hp++) {
        float a, b; upk(acc[hp], a, b);
        rp[2*hp] = a; rp[2*hp+1] = b;
    }
}

// ---------------- kernel 3: reduce j-splits + output MLP + partial stats ----------------
__global__ void k_outfeat(const float* __restrict__ W1, const float* __restrict__ b1,
                          const float* __restrict__ W2, const float* __restrict__ b2) {
    __shared__ float4 W1s[256];
    __shared__ float4 W2s[64];
    __shared__ float  b1s[16], b2s[16];
    __shared__ float  red[4][8];
    int tid = threadIdx.x;
    for (int t = tid; t < 256; t += 128) W1s[t] = ((const float4*)W1)[t];
    if (tid < 64) W2s[tid] = ((const float4*)W2)[tid];
    if (tid < 16) { b1s[tid] = b1[tid]; b2s[tid] = b2[tid]; }
    __syncthreads();

    int p = blockIdx.x * 128 + tid;
    float4 r4[16];
    #pragma unroll
    for (int k = 0; k < 16; k++) r4[k] = g_respart4[(size_t)p * 16 + k];
    for (int s = 1; s < JSPLIT; s++)
        #pragma unroll
        for (int k = 0; k < 16; k++) {
            float4 v = g_respart4[((size_t)s * NPTS + p) * 16 + k];
            r4[k].x += v.x; r4[k].y += v.y; r4[k].z += v.z; r4[k].w += v.w;
        }

    float o1[16];
    #pragma unroll
    for (int h = 0; h < 16; h++) {
        float s = b1s[h];
        #pragma unroll
        for (int k = 0; k < 16; k++) {
            float4 w = W1s[h * 16 + k]; float4 v = r4[k];
            s = fmaf(w.x, v.x, fmaf(w.y, v.y, fmaf(w.z, v.z, fmaf(w.w, v.w, s))));
        }
        o1[h] = leaky(s);
    }

    float gs[4] = {0,0,0,0}, gq[4] = {0,0,0,0};
    #pragma unroll
    for (int h = 0; h < 16; h++) {
        float s = b2s[h];
        #pragma unroll
        for (int k4 = 0; k4 < 4; k4++) {
            float4 w = W2s[h * 4 + k4];
            s = fmaf(w.x, o1[k4*4+0], fmaf(w.y, o1[k4*4+1], fmaf(w.z, o1[k4*4+2], fmaf(w.w, o1[k4*4+3], s))));
        }
        float v = leaky(s);
        g_opre[p * 16 + h] = v;
        int g = h >> 2; gs[g] += v; gq[g] += v * v;
    }

    int w = tid >> 5, l = tid & 31;
    #pragma unroll
    for (int g = 0; g < 4; g++) {
        float s = warp_sum(gs[g]);
        float q = warp_sum(gq[g]);
        if (l == 0) { red[w][g*2] = s; red[w][g*2+1] = q; }
    }
    __syncthreads();
    if (tid < 8) g_pout[blockIdx.x * 8 + tid] = red[0][tid] + red[1][tid] + red[2][tid] + red[3][tid];
}

// ---------------- kernel 4: final GroupNorm -> d_out (inline stats) ----------------
__global__ void k_onorm(float* __restrict__ out,
                        const float* __restrict__ gout, const float* __restrict__ bout) {
    __shared__ float2 s_st[4];
    int tid = threadIdx.x;
    if (tid < 4) {
        float s = 0.f, q = 0.f;
        for (int b = 0; b < 32; b++) { s += g_pout[b*8 + tid*2]; q += g_pout[b*8 + tid*2 + 1]; }
        float mu  = s * (1.0f / 16384.0f);
        float var = q * (1.0f / 16384.0f) - mu * mu;
        s_st[tid] = make_float2(mu, rsqrtf(var + 1e-5f));
    }
    __syncthreads();
    int idx = blockIdx.x * 256 + tid;
    int h = idx & 15, g = h >> 2;
    float2 st = s_st[g];
    out[idx] = (g_opre[idx] - st.x) * st.y * gout[h] + bout[h];
}

// ---------------- launch ----------------
extern "C" void kernel_launch(void* const* d_in, const int* in_sizes, int n_in,
                              void* d_out, int out_size) {
    const float* points   = (const float*)d_in[0];
    const float* nuv      = (const float*)d_in[1];
    const float* features = (const float*)d_in[2];
    const float* W_in1    = (const float*)d_in[3];
    const float* b_in1    = (const float*)d_in[4];
    const float* W_in2    = (const float*)d_in[5];
    const float* b_in2    = (const float*)d_in[6];
    const float* g_in     = (const float*)d_in[7];
    const float* beta_in  = (const float*)d_in[8];
    const float* A1       = (const float*)d_in[9];
    const float* B1       = (const float*)d_in[10];
    const float* A2       = (const float*)d_in[11];
    const float* B2       = (const float*)d_in[12];
    const float* W_out1   = (const float*)d_in[13];
    const float* b_out1   = (const float*)d_in[14];
    const float* W_out2   = (const float*)d_in[15];
    const float* b_out2   = (const float*)d_in[16];
    const float* g_out    = (const float*)d_in[17];
    const float* beta_out = (const float*)d_in[18];
    float* out = (float*)d_out;

    static int smem_set = 0;
    if (!smem_set) {
        cudaFuncSetAttribute(k_conv, cudaFuncAttributeMaxDynamicSharedMemorySize, SMEM_DYN);
        smem_set = 1;
    }

    k_infeat <<<32, 128>>>(features, W_in1, b_in1, W_in2, b_in2);
    k_conv   <<<dim3(NPTS / 64, JSPLIT), 256, SMEM_DYN>>>(points, nuv, A1, B1, A2, B2, g_in, beta_in);
    k_outfeat<<<32, 128>>>(W_out1, b_out1, W_out2, b_out2);
    k_onorm  <<<NPTS * ODIM / 256, 256>>>(out, g_out, beta_out);
}

// round 17
// speedup vs baseline: 1.0886x; 1.0886x over previous
#include <cuda_runtime.h>

// ---------------- problem dims ----------------
#define NPTS   4096
#define HDIM   64
#define ODIM   16
#define JSPLIT 16
#define JRANGE (NPTS / JSPLIT)   // 256 — whole range staged once

typedef unsigned long long ull;

// ---------------- dynamic smem layout (bytes) ----------------
#define OFF_SP   0                      // float4[256]  (4 KB)
#define OFF_SN   4096                   // float4[256]  (4 KB)
#define OFF_SFQ  8192                   // ull[256*32]  (64 KB)
#define OFF_A2   73728                  // float[512]
#define OFF_B2   75776                  // float[64]
#define OFF_A1   76032                  // float[24]
#define OFF_B1   76128                  // float[8]
#define OFF_QA   76160                  // ull[32]  per-h-pair scale
#define OFF_QB   76416                  // ull[32]  per-h-pair bias
#define OFF_ST   76672                  // float2[4]
#define SMEM_DYN 76736

// ---------------- f32x2 helpers ----------------
static __device__ __forceinline__ ull pk(float a, float b) {
    ull r; asm("mov.b64 %0, {%1, %2};" : "=l"(r) : "f"(a), "f"(b)); return r;
}
static __device__ __forceinline__ void upk(ull x, float& a, float& b) {
    asm("mov.b64 {%0, %1}, %2;" : "=f"(a), "=f"(b) : "l"(x));
}
static __device__ __forceinline__ ull fma2(ull a, ull b, ull c) {
    ull d; asm("fma.rn.f32x2 %0, %1, %2, %3;" : "=l"(d) : "l"(a), "l"(b), "l"(c)); return d;
}
static __device__ __forceinline__ ull mul2(ull a, ull b) {
    ull d; asm("mul.rn.f32x2 %0, %1, %2;" : "=l"(d) : "l"(a), "l"(b)); return d;
}
static __device__ __forceinline__ float ex2(float x) {
    float r; asm("ex2.approx.f32 %0, %1;" : "=f"(r) : "f"(x)); return r;
}
static __device__ __forceinline__ float leaky(float x) { return fmaxf(x, 0.2f * x); }

static __device__ __forceinline__ float warp_sum(float v) {
    #pragma unroll
    for (int o = 16; o; o >>= 1) v += __shfl_down_sync(0xffffffffu, v, o);
    return v;
}

// coords pre-scaled by S*sqrt(log2 e), M by 1/sqrt(log2 e): folds L2E into sq
#define SLC  0.84932180028801904f
#define MINV 0.83255461115769769f

// ---------------- scratch ----------------
__device__ float  g_fpre[NPTS * HDIM];
__device__ float4 g_respart4[JSPLIT * NPTS * HDIM / 4];
__device__ float4 g_res4[NPTS * HDIM / 4];      // j-split-reduced result
__device__ float  g_opre[NPTS * ODIM];
__device__ float  g_pin[32 * 8];
__device__ float  g_pout[32 * 8];

// ---------------- kernel 1: input MLP (16->64->64) + partial group stats ----------------
__global__ void k_infeat(const float* __restrict__ feat,
                         const float* __restrict__ W1, const float* __restrict__ b1,
                         const float* __restrict__ W2, const float* __restrict__ b2) {
    __shared__ float4 W1s[256];
    __shared__ float4 W2s[1024];
    __shared__ float  b1s[64], b2s[64];
    __shared__ float  red[4][8];
    int tid = threadIdx.x;
    for (int t = tid; t < 256;  t += 128) W1s[t] = ((const float4*)W1)[t];
    for (int t = tid; t < 1024; t += 128) W2s[t] = ((const float4*)W2)[t];
    if (tid < 64) { b1s[tid] = b1[tid]; b2s[tid] = b2[tid]; }
    __syncthreads();

    int p = blockIdx.x * 128 + tid;
    float f[16];
    #pragma unroll
    for (int k = 0; k < 16; k++) f[k] = feat[p * 16 + k];

    float t1[64];
    #pragma unroll
    for (int h = 0; h < 64; h++) {
        float s = b1s[h];
        #pragma unroll
        for (int k4 = 0; k4 < 4; k4++) {
            float4 w = W1s[h * 4 + k4];
            s = fmaf(w.x, f[k4*4+0], fmaf(w.y, f[k4*4+1], fmaf(w.z, f[k4*4+2], fmaf(w.w, f[k4*4+3], s))));
        }
        t1[h] = leaky(s);
    }

    float gs[4] = {0,0,0,0}, gq[4] = {0,0,0,0};
    for (int h = 0; h < 64; h++) {
        float s = b2s[h];
        #pragma unroll
        for (int k4 = 0; k4 < 16; k4++) {
            float4 w = W2s[h * 16 + k4];
            s = fmaf(w.x, t1[k4*4+0], fmaf(w.y, t1[k4*4+1], fmaf(w.z, t1[k4*4+2], fmaf(w.w, t1[k4*4+3], s))));
        }
        float v = leaky(s);
        g_fpre[p * 64 + h] = v;
        int g = h >> 4; gs[g] += v; gq[g] += v * v;
    }

    int w = tid >> 5, l = tid & 31;
    #pragma unroll
    for (int g = 0; g < 4; g++) {
        float s = warp_sum(gs[g]);
        float q = warp_sum(gq[g]);
        if (l == 0) { red[w][g*2] = s; red[w][g*2+1] = q; }
    }
    __syncthreads();
    if (tid < 8) g_pin[blockIdx.x * 8 + tid] = red[0][tid] + red[1][tid] + red[2][tid] + red[3][tid];
}

// ---------------- kernel 2: pairwise convolution (single-tile, shuffle-pipelined) ----------------
// Warp = 8 i x 4 h-lanes. Cooperative scalar block (1 j per h-lane), shuffles for
// j+1 issued during j's matvec. Whole 256-j range staged ONCE in dynamic smem.
__global__ void __launch_bounds__(128, 2) k_conv(
        const float* __restrict__ points, const float* __restrict__ nuvp,
        const float* __restrict__ A1, const float* __restrict__ B1,
        const float* __restrict__ A2, const float* __restrict__ B2,
        const float* __restrict__ gin, const float* __restrict__ bin) {
    extern __shared__ char smem[];
    float4* sp   = (float4*)(smem + OFF_SP);
    float4* sn   = (float4*)(smem + OFF_SN);
    ull*    sfq  = (ull*)   (smem + OFF_SFQ);
    float*  s_A2 = (float*) (smem + OFF_A2);
    float*  s_B2 = (float*) (smem + OFF_B2);
    float*  s_A1 = (float*) (smem + OFF_A1);
    float*  s_B1 = (float*) (smem + OFF_B1);
    ull*    s_a2 = (ull*)   (smem + OFF_QA);
    ull*    s_b2 = (ull*)   (smem + OFF_QB);
    float2* s_st = (float2*)(smem + OFF_ST);

    int tid = threadIdx.x;
    int warp = tid >> 5, lane = tid & 31, isub = lane & 7, hl = lane >> 3;
    int i  = blockIdx.x * 32 + warp * 8 + isub;
    int h0 = hl * 16;

    // ---- cooperative param staging (cheap per-block prologue) ----
    ((float4*)s_A2)[tid] = ((const float4*)A2)[tid];          // 512 floats
    if (tid < 16) ((float4*)s_B2)[tid] = ((const float4*)B2)[tid];
    if (tid < 24) s_A1[tid] = A1[tid];
    if (tid < 8)  s_B1[tid] = B1[tid];

    // ---- inline GroupNorm stats for f (deterministic fixed-order) ----
    if (tid < 4) {
        float s = 0.f, q = 0.f;
        for (int b = 0; b < 32; b++) { s += g_pin[b*8 + tid*2]; q += g_pin[b*8 + tid*2 + 1]; }
        float mu  = s * (1.0f / 65536.0f);
        float var = q * (1.0f / 65536.0f) - mu * mu;
        s_st[tid] = make_float2(mu, rsqrtf(var + 1e-5f));
    }
    __syncthreads();
    if (tid < 32) {
        int ha = tid * 2, hb = ha + 1;
        float2 sa = s_st[ha >> 4], sb = s_st[hb >> 4];
        float Aa = sa.y * gin[ha], Ab = sb.y * gin[hb];
        s_a2[tid] = pk(Aa, Ab);
        s_b2[tid] = pk(bin[ha] - sa.x * Aa, bin[hb] - sb.x * Ab);
    }

    float pix = points[3*i+0]*SLC, piy = points[3*i+1]*SLC, piz = points[3*i+2]*SLC;
    float nix = nuvp[9*i+0],       niy = nuvp[9*i+1],       niz = nuvp[9*i+2];
    float m2x = -2.0f*pix, m2y = -2.0f*piy, m2z = -2.0f*piz;
    float bsq = pix*pix + piy*piy + piz*piz;

    // M = (A1 @ nuv_i)/sqrt(log2 e); bb = B1 - M . ci   (params from smem)
    float M[8][3], bb[8];
    #pragma unroll
    for (int c = 0; c < 8; c++) {
        float a0 = s_A1[c*3+0], a1 = s_A1[c*3+1], a2c = s_A1[c*3+2];
        #pragma unroll
        for (int d = 0; d < 3; d++)
            M[c][d] = fmaf(a0, nuvp[9*i + d], fmaf(a1, nuvp[9*i + 3 + d], a2c * nuvp[9*i + 6 + d])) * MINV;
        bb[c] = s_B1[c] - (M[c][0]*pix + M[c][1]*piy + M[c][2]*piz);
    }

    // per-lane A2 slice (h-pairs) + B2, built from smem
    ull a2r[8][8];
    #pragma unroll
    for (int hp = 0; hp < 8; hp++)
        #pragma unroll
        for (int c = 0; c < 8; c++)
            a2r[c][hp] = pk(s_A2[(h0 + 2*hp) * 8 + c], s_A2[(h0 + 2*hp + 1) * 8 + c]);
    ull b2p[8];
    #pragma unroll
    for (int hp = 0; hp < 8; hp++) b2p[hp] = pk(s_B2[h0 + 2*hp], s_B2[h0 + 2*hp + 1]);

    ull acc[8];
    #pragma unroll
    for (int hp = 0; hp < 8; hp++) acc[hp] = pk(0.f, 0.f);

    // ---- stage whole j-range ONCE ----
    int j0 = blockIdx.y * JRANGE;
    for (int t = tid; t < JRANGE; t += 128) {
        int j = j0 + t;
        float px = points[3*j]*SLC, py = points[3*j+1]*SLC, pz = points[3*j+2]*SLC;
        sp[t] = make_float4(px, py, pz, px*px + py*py + pz*pz);
        sn[t] = make_float4(nuvp[9*j], nuvp[9*j+1], nuvp[9*j+2], 0.f);
    }
    __syncthreads();   // s_a2/s_b2 visible for f staging
    for (int t = tid; t < JRANGE * 16; t += 128) {
        ulonglong2 r = ((const ulonglong2*)g_fpre)[(size_t)j0 * 16 + t];
        int hp2 = (t & 15) * 2;
        float a, b, c, d;
        upk(r.x, a, b); upk(r.y, c, d);
        float Aa, Ab, Ba, Bb, Ac, Ad, Bc, Bd;
        upk(s_a2[hp2], Aa, Ab);     upk(s_b2[hp2], Ba, Bb);
        upk(s_a2[hp2 + 1], Ac, Ad); upk(s_b2[hp2 + 1], Bc, Bd);
        ulonglong2 w2;
        w2.x = pk(fmaf(a, Aa, Ba), fmaf(b, Ab, Bb));
        w2.y = pk(fmaf(c, Ac, Bc), fmaf(d, Ad, Bd));
        ((ulonglong2*)sfq)[t] = w2;
    }
    __syncthreads();

    // ---- barrier-free mainloop over 256 j ----
    // prologue: scalar block for group 0, then prime the q=0 shuffles
    float wA, ysA[8];
    {
        float4 pj = sp[hl], nj = sn[hl];
        float sq = fmaf(m2x, pj.x, fmaf(m2y, pj.y, fmaf(m2z, pj.z, bsq + pj.w)));
        float dt = fmaf(nix, nj.x, fmaf(niy, nj.y, niz * nj.z));
        wA = ex2(sq * (2.0f - dt) * (dt - 2.0f));
        #pragma unroll
        for (int c = 0; c < 8; c++) {
            float y = fmaf(M[c][0], pj.x, fmaf(M[c][1], pj.y, fmaf(M[c][2], pj.z, bb[c])));
            ysA[c] = fmaxf(y, 0.f);
        }
    }
    float wvC = __shfl_sync(0xffffffffu, wA, isub);
    float yvC[8];
    #pragma unroll
    for (int c = 0; c < 8; c++) yvC[c] = __shfl_sync(0xffffffffu, ysA[c], isub);

    #pragma unroll 1
    for (int g = 0; g < JRANGE / 4; g++) {
        // ---- compute NEXT group's scalar block first (hides its latency) ----
        float wB, ysB[8];
        {
            int jn = (g + 1 < JRANGE / 4) ? (g + 1) * 4 + hl : hl;   // last iter: dummy
            float4 pj = sp[jn], nj = sn[jn];
            float sq = fmaf(m2x, pj.x, fmaf(m2y, pj.y, fmaf(m2z, pj.z, bsq + pj.w)));
            float dt = fmaf(nix, nj.x, fmaf(niy, nj.y, niz * nj.z));
            wB = ex2(sq * (2.0f - dt) * (dt - 2.0f));
            #pragma unroll
            for (int c = 0; c < 8; c++) {
                float y = fmaf(M[c][0], pj.x, fmaf(M[c][1], pj.y, fmaf(M[c][2], pj.z, bb[c])));
                ysB[c] = fmaxf(y, 0.f);
            }
        }

        // ---- consume 4 j's; shuffles for j+1 issued before j's matvec ----
        int jj4 = g * 4;
        #pragma unroll
        for (int q = 0; q < 4; q++) {
            // prefetch next j's scalars (q<3: group A src q+1; q==3: group B src 0)
            float wvN;
            float yvN[8];
            if (q < 3) {
                int src = isub + ((q + 1) << 3);
                wvN = __shfl_sync(0xffffffffu, wA, src);
                #pragma unroll
                for (int c = 0; c < 8; c++) yvN[c] = __shfl_sync(0xffffffffu, ysA[c], src);
            } else {
                wvN = __shfl_sync(0xffffffffu, wB, isub);
                #pragma unroll
                for (int c = 0; c < 8; c++) yvN[c] = __shfl_sync(0xffffffffu, ysB[c], isub);
            }

            int jj = jj4 + q;
            ull ys[8];
            #pragma unroll
            for (int c = 0; c < 8; c++) ys[c] = pk(yvC[c], yvC[c]);

            // matvec: G = A2.Y + B2, 8 independent packed chains
            ull gg[8];
            #pragma unroll
            for (int hp = 0; hp < 8; hp++) gg[hp] = fma2(a2r[0][hp], ys[0], b2p[hp]);
            #pragma unroll
            for (int c = 1; c < 8; c++)
                #pragma unroll
                for (int hp = 0; hp < 8; hp++) gg[hp] = fma2(a2r[c][hp], ys[c], gg[hp]);

            // epilogue: acc += relu(G) * f * w   (f via LDS.128)
            const ulonglong2* f2 = (const ulonglong2*)(sfq + jj * 32 + hl * 8);
            ulonglong2 fq0 = f2[0], fq1 = f2[1], fq2 = f2[2], fq3 = f2[3];
            ull frow[8] = {fq0.x, fq0.y, fq1.x, fq1.y, fq2.x, fq2.y, fq3.x, fq3.y};
            ull ws = pk(wvC, wvC);
            #pragma unroll
            for (int hp = 0; hp < 8; hp++) {
                float a, b; upk(gg[hp], a, b);
                a = fmaxf(a, 0.f); b = fmaxf(b, 0.f);
                acc[hp] = fma2(mul2(pk(a, b), frow[hp]), ws, acc[hp]);
            }

            wvC = wvN;
            #pragma unroll
            for (int c = 0; c < 8; c++) yvC[c] = yvN[c];
        }

        wA = wB;
        #pragma unroll
        for (int c = 0; c < 8; c++) ysA[c] = ysB[c];
    }

    float* rp = ((float*)g_respart4) + ((size_t)blockIdx.y * NPTS + i) * 64 + h0;
    #pragma unroll
    for (int hp = 0; hp < 8; hp++) {
        float a, b; upk(acc[hp], a, b);
        rp[2*hp] = a; rp[2*hp+1] = b;
    }
}

// ---------------- kernel 3: wide j-split reduction (full-chip) ----------------
__global__ void k_reduce() {
    int idx = blockIdx.x * 256 + threadIdx.x;     // 0 .. NPTS*16-1 (float4 lanes)
    float4 r = g_respart4[idx];
    #pragma unroll
    for (int s = 1; s < JSPLIT; s++) {
        float4 v = g_respart4[s * (NPTS * 16) + idx];
        r.x += v.x; r.y += v.y; r.z += v.z; r.w += v.w;
    }
    g_res4[idx] = r;
}

// ---------------- kernel 4: output MLP (64->16->16) + partial stats ----------------
__global__ void k_outfeat(const float* __restrict__ W1, const float* __restrict__ b1,
                          const float* __restrict__ W2, const float* __restrict__ b2) {
    __shared__ float4 W1s[256];
    __shared__ float4 W2s[64];
    __shared__ float  b1s[16], b2s[16];
    __shared__ float  red[4][8];
    int tid = threadIdx.x;
    for (int t = tid; t < 256; t += 128) W1s[t] = ((const float4*)W1)[t];
    if (tid < 64) W2s[tid] = ((const float4*)W2)[tid];
    if (tid < 16) { b1s[tid] = b1[tid]; b2s[tid] = b2[tid]; }
    __syncthreads();

    int p = blockIdx.x * 128 + tid;
    float4 r4[16];
    #pragma unroll
    for (int k = 0; k < 16; k++) r4[k] = g_res4[(size_t)p * 16 + k];

    float o1[16];
    #pragma unroll
    for (int h = 0; h < 16; h++) {
        float s = b1s[h];
        #pragma unroll
        for (int k = 0; k < 16; k++) {
            float4 w = W1s[h * 16 + k]; float4 v = r4[k];
            s = fmaf(w.x, v.x, fmaf(w.y, v.y, fmaf(w.z, v.z, fmaf(w.w, v.w, s))));
        }
        o1[h] = leaky(s);
    }

    float gs[4] = {0,0,0,0}, gq[4] = {0,0,0,0};
    #pragma unroll
    for (int h = 0; h < 16; h++) {
        float s = b2s[h];
        #pragma unroll
        for (int k4 = 0; k4 < 4; k4++) {
            float4 w = W2s[h * 4 + k4];
            s = fmaf(w.x, o1[k4*4+0], fmaf(w.y, o1[k4*4+1], fmaf(w.z, o1[k4*4+2], fmaf(w.w, o1[k4*4+3], s))));
        }
        float v = leaky(s);
        g_opre[p * 16 + h] = v;
        int g = h >> 2; gs[g] += v; gq[g] += v * v;
    }

    int w = tid >> 5, l = tid & 31;
    #pragma unroll
    for (int g = 0; g < 4; g++) {
        float s = warp_sum(gs[g]);
        float q = warp_sum(gq[g]);
        if (l == 0) { red[w][g*2] = s; red[w][g*2+1] = q; }
    }
    __syncthreads();
    if (tid < 8) g_pout[blockIdx.x * 8 + tid] = red[0][tid] + red[1][tid] + red[2][tid] + red[3][tid];
}

// ---------------- kernel 5: final GroupNorm -> d_out (inline stats) ----------------
__global__ void k_onorm(float* __restrict__ out,
                        const float* __restrict__ gout, const float* __restrict__ bout) {
    __shared__ float2 s_st[4];
    int tid = threadIdx.x;
    if (tid < 4) {
        float s = 0.f, q = 0.f;
        for (int b = 0; b < 32; b++) { s += g_pout[b*8 + tid*2]; q += g_pout[b*8 + tid*2 + 1]; }
        float mu  = s * (1.0f / 16384.0f);
        float var = q * (1.0f / 16384.0f) - mu * mu;
        s_st[tid] = make_float2(mu, rsqrtf(var + 1e-5f));
    }
    __syncthreads();
    int idx = blockIdx.x * 256 + tid;
    int h = idx & 15, g = h >> 2;
    float2 st = s_st[g];
    out[idx] = (g_opre[idx] - st.x) * st.y * gout[h] + bout[h];
}

// ---------------- launch ----------------
extern "C" void kernel_launch(void* const* d_in, const int* in_sizes, int n_in,
                              void* d_out, int out_size) {
    const float* points   = (const float*)d_in[0];
    const float* nuv      = (const float*)d_in[1];
    const float* features = (const float*)d_in[2];
    const float* W_in1    = (const float*)d_in[3];
    const float* b_in1    = (const float*)d_in[4];
    const float* W_in2    = (const float*)d_in[5];
    const float* b_in2    = (const float*)d_in[6];
    const float* g_in     = (const float*)d_in[7];
    const float* beta_in  = (const float*)d_in[8];
    const float* A1       = (const float*)d_in[9];
    const float* B1       = (const float*)d_in[10];
    const float* A2       = (const float*)d_in[11];
    const float* B2       = (const float*)d_in[12];
    const float* W_out1   = (const float*)d_in[13];
    const float* b_out1   = (const float*)d_in[14];
    const float* W_out2   = (const float*)d_in[15];
    const float* b_out2   = (const float*)d_in[16];
    const float* g_out    = (const float*)d_in[17];
    const float* beta_out = (const float*)d_in[18];
    float* out = (float*)d_out;

    static int smem_set = 0;
    if (!smem_set) {
        cudaFuncSetAttribute(k_conv, cudaFuncAttributeMaxDynamicSharedMemorySize, SMEM_DYN);
        smem_set = 1;
    }

    k_infeat <<<32, 128>>>(features, W_in1, b_in1, W_in2, b_in2);
    k_conv   <<<dim3(NPTS / 32, JSPLIT), 128, SMEM_DYN>>>(points, nuv, A1, B1, A2, B2, g_in, beta_in);
    k_reduce <<<NPTS * 16 / 256, 256>>>();
    k_outfeat<<<32, 128>>>(W_out1, b_out1, W_out2, b_out2);
    k_onorm  <<<NPTS * ODIM / 256, 256>>>(out, g_out, beta_out);
}